// round 17
// baseline (speedup 1.0000x reference)
#include <cuda_runtime.h>
#include <cuda_fp16.h>
#include <math.h>
#include <stdint.h>

#define N_NODES 50000
#define MPAD    50048   // 391 * 128
#define E0      800000
#define NE      850000
#define F_IN    1433
#define K1PAD   1472    // 46 * 32
#define H1      512
#define H2      256
#define NC      7
#define NB      196     // ceil(N_NODES / 256)

// ==================== scratch (device globals) ====================
__device__ int8_t g_A8[(size_t)MPAD * K1PAD];
__device__ int8_t g_B8[(size_t)H1 * K1PAD];
__device__ float  g_sAinv[MPAD];
__device__ float  g_sBinv[H1];
__device__ __half g_h16[(size_t)MPAD * H1];
__device__ __half g_A16[(size_t)MPAD * H1];
__device__ __half g_B16b[(size_t)H2 * H1];
__device__ float g_buf1[(size_t)MPAD * NC];
__device__ float g_buf2[(size_t)MPAD * H2];
__device__ float g_ss[N_NODES];
__device__ float g_sd[N_NODES];
__device__ float g_alpha[NE];
__device__ int   g_src[NE];
__device__ int   g_dst[NE];
__device__ int   g_csr_src[NE];
__device__ int   g_deg[N_NODES];
__device__ int   g_rowoff[N_NODES + 1];
__device__ int   g_cursor[N_NODES];
__device__ int   g_bsum[NB];
__device__ int   g_boff[NB];
__device__ int   g_is64;

// ==================== PTX helpers (base-arch only) ====================
__device__ __forceinline__ uint32_t smem_u32(const void* p) {
    uint32_t a;
    asm("{ .reg .u64 t; cvta.to.shared.u64 t, %1; cvt.u32.u64 %0, t; }" : "=r"(a) : "l"(p));
    return a;
}
__device__ __forceinline__ void cp16(uint32_t dst, const void* src) {
    asm volatile("cp.async.cg.shared.global [%0], [%1], 16;" :: "r"(dst), "l"(src));
}
__device__ __forceinline__ int lds32(uint32_t addr) {
    int v;
    asm volatile("ld.shared.b32 %0, [%1];" : "=r"(v) : "r"(addr));
    return v;
}
__device__ __forceinline__ void ldm_x4(uint32_t& r0, uint32_t& r1, uint32_t& r2, uint32_t& r3,
                                       uint32_t addr) {
    asm volatile("ldmatrix.sync.aligned.m8n8.x4.shared.b16 {%0,%1,%2,%3}, [%4];"
                 : "=r"(r0), "=r"(r1), "=r"(r2), "=r"(r3) : "r"(addr));
}
__device__ __forceinline__ void mma_f16(float* c, const uint32_t* a, const uint32_t* b) {
    asm volatile("mma.sync.aligned.m16n8k16.row.col.f32.f16.f16.f32 "
                 "{%0,%1,%2,%3}, {%4,%5,%6,%7}, {%8,%9}, {%0,%1,%2,%3};"
                 : "+f"(c[0]), "+f"(c[1]), "+f"(c[2]), "+f"(c[3])
                 : "r"(a[0]), "r"(a[1]), "r"(a[2]), "r"(a[3]), "r"(b[0]), "r"(b[1]));
}
__device__ __forceinline__ void mma_s8(int* c, const int* a, const int* b) {
    asm volatile("mma.sync.aligned.m16n8k32.row.col.s32.s8.s8.s32 "
                 "{%0,%1,%2,%3}, {%4,%5,%6,%7}, {%8,%9}, {%0,%1,%2,%3};"
                 : "+r"(c[0]), "+r"(c[1]), "+r"(c[2]), "+r"(c[3])
                 : "r"(a[0]), "r"(a[1]), "r"(a[2]), "r"(a[3]), "r"(b[0]), "r"(b[1]));
}

// fused score epilogue used by fp16 layer-2 GEMM
__device__ __forceinline__ void epilogue_scores(
    const float acc[2][8][4], const float* __restrict__ a_s, const float* __restrict__ a_d,
    int m0, int n0, int warp_m, int warp_n, int lane) {
    const int er = lane >> 2, ec = (lane & 3) * 2;
    #pragma unroll
    for (int mi = 0; mi < 2; mi++) {
        float ss0 = 0.f, ss1 = 0.f, sd0 = 0.f, sd1 = 0.f;
        #pragma unroll
        for (int ni = 0; ni < 8; ni++) {
            const int cc = n0 + warp_n * 64 + ni * 8 + ec;
            float as0 = a_s[cc], as1 = a_s[cc + 1];
            float ad0 = a_d[cc], ad1 = a_d[cc + 1];
            ss0 += acc[mi][ni][0] * as0 + acc[mi][ni][1] * as1;
            ss1 += acc[mi][ni][2] * as0 + acc[mi][ni][3] * as1;
            sd0 += acc[mi][ni][0] * ad0 + acc[mi][ni][1] * ad1;
            sd1 += acc[mi][ni][2] * ad0 + acc[mi][ni][3] * ad1;
        }
        #pragma unroll
        for (int o = 1; o <= 2; o <<= 1) {
            ss0 += __shfl_xor_sync(0xffffffffu, ss0, o);
            ss1 += __shfl_xor_sync(0xffffffffu, ss1, o);
            sd0 += __shfl_xor_sync(0xffffffffu, sd0, o);
            sd1 += __shfl_xor_sync(0xffffffffu, sd1, o);
        }
        if ((lane & 3) == 0) {
            int r0 = m0 + warp_m * 32 + mi * 16 + er;
            int r1 = r0 + 8;
            if (r0 < N_NODES) { atomicAdd(&g_ss[r0], ss0); atomicAdd(&g_sd[r0], sd0); }
            if (r1 < N_NODES) { atomicAdd(&g_ss[r1], ss1); atomicAdd(&g_sd[r1], sd1); }
        }
    }
}

// ==================== edge prep + CSR build ====================
__global__ void init_kernel(const unsigned int* __restrict__ w) {
    if (blockIdx.x == 0) {
        __shared__ int nz;
        if (threadIdx.x == 0) nz = 0;
        __syncthreads();
        if (threadIdx.x < 128 && w[threadIdx.x * 2 + 1] != 0u) atomicOr(&nz, 1);
        __syncthreads();
        if (threadIdx.x == 0) g_is64 = (nz == 0);
    }
    int i = blockIdx.x * blockDim.x + threadIdx.x;
    if (i < N_NODES) g_deg[i] = 0;
}

__global__ void zero_s_kernel() {
    int i = blockIdx.x * blockDim.x + threadIdx.x;
    if (i < N_NODES) {
        g_ss[i] = 0.0f;
        g_sd[i] = 0.0f;
    }
}

__global__ void prep_edges_kernel(const void* __restrict__ ei) {
    int i = blockIdx.x * blockDim.x + threadIdx.x;
    if (i >= NE) return;
    int s, d;
    if (i < E0) {
        if (g_is64) {
            const long long* e = (const long long*)ei;
            s = (int)e[i]; d = (int)e[E0 + i];
        } else {
            const int* e = (const int*)ei;
            s = e[i]; d = e[E0 + i];
        }
    } else {
        s = d = i - E0;
    }
    s = min(max(s, 0), N_NODES - 1);
    d = min(max(d, 0), N_NODES - 1);
    g_src[i] = s;
    g_dst[i] = d;
    atomicAdd(&g_deg[d], 1);
}

__global__ void reduce_deg_kernel() {
    __shared__ int sh[256];
    int i = blockIdx.x * 256 + threadIdx.x;
    sh[threadIdx.x] = (i < N_NODES) ? g_deg[i] : 0;
    __syncthreads();
    for (int o = 128; o > 0; o >>= 1) {
        if (threadIdx.x < o) sh[threadIdx.x] += sh[threadIdx.x + o];
        __syncthreads();
    }
    if (threadIdx.x == 0) g_bsum[blockIdx.x] = sh[0];
}

__global__ void scan_bsums_kernel() {
    __shared__ int sh[256];
    int t = threadIdx.x;
    int mine = (t < NB) ? g_bsum[t] : 0;
    sh[t] = mine;
    __syncthreads();
    for (int o = 1; o < 256; o <<= 1) {
        int v = (t >= o) ? sh[t - o] : 0;
        __syncthreads();
        sh[t] += v;
        __syncthreads();
    }
    if (t < NB) g_boff[t] = sh[t] - mine;
    if (t == 0) g_rowoff[N_NODES] = NE;
}

__global__ void scan_write_kernel() {
    __shared__ int sh[256];
    int i = blockIdx.x * 256 + threadIdx.x;
    int v = (i < N_NODES) ? g_deg[i] : 0;
    sh[threadIdx.x] = v;
    __syncthreads();
    for (int o = 1; o < 256; o <<= 1) {
        int u = (threadIdx.x >= o) ? sh[threadIdx.x - o] : 0;
        __syncthreads();
        sh[threadIdx.x] += u;
        __syncthreads();
    }
    if (i < N_NODES) {
        int excl = g_boff[blockIdx.x] + sh[threadIdx.x] - v;
        g_rowoff[i] = excl;
        g_cursor[i] = excl;
    }
}

__global__ void scatter_kernel() {
    int i = blockIdx.x * blockDim.x + threadIdx.x;
    if (i >= NE) return;
    int pos = atomicAdd(&g_cursor[g_dst[i]], 1);
    g_csr_src[pos] = g_src[i];
}

// ==================== quantization prepasses ====================
// block per row of x: per-row max -> int8 quantize into g_A8
__global__ void __launch_bounds__(256)
rowquant_kernel(const float* __restrict__ x) {
    __shared__ float sh[256];
    int row = blockIdx.x;
    int8_t* q = g_A8 + (size_t)row * K1PAD;
    if (row >= N_NODES) {
        for (int k = threadIdx.x; k < K1PAD; k += 256) q[k] = 0;
        if (threadIdx.x == 0) g_sAinv[row] = 0.0f;
        return;
    }
    const float* xr = x + (size_t)row * F_IN;
    float mx = 0.0f;
    for (int k = threadIdx.x; k < F_IN; k += 256) mx = fmaxf(mx, fabsf(xr[k]));
    sh[threadIdx.x] = mx;
    __syncthreads();
    for (int o = 128; o > 0; o >>= 1) {
        if (threadIdx.x < o) sh[threadIdx.x] = fmaxf(sh[threadIdx.x], sh[threadIdx.x + o]);
        __syncthreads();
    }
    mx = sh[0];
    float s = (mx > 1e-30f) ? 127.0f / mx : 0.0f;
    for (int k = threadIdx.x; k < K1PAD; k += 256) {
        float v = (k < F_IN) ? xr[k] * s : 0.0f;
        int qi = __float2int_rn(v);
        qi = min(max(qi, -127), 127);
        q[k] = (int8_t)qi;
    }
    if (threadIdx.x == 0) g_sAinv[row] = (mx > 1e-30f) ? mx / 127.0f : 0.0f;
}

// block per column n of W1: per-col max -> int8 quantize (transposed, K-major)
__global__ void __launch_bounds__(256)
wquant_kernel(const float* __restrict__ W) {
    __shared__ float sh[256];
    int n = blockIdx.x;
    float mx = 0.0f;
    for (int k = threadIdx.x; k < F_IN; k += 256) mx = fmaxf(mx, fabsf(W[(size_t)k * H1 + n]));
    sh[threadIdx.x] = mx;
    __syncthreads();
    for (int o = 128; o > 0; o >>= 1) {
        if (threadIdx.x < o) sh[threadIdx.x] = fmaxf(sh[threadIdx.x], sh[threadIdx.x + o]);
        __syncthreads();
    }
    mx = sh[0];
    float s = (mx > 1e-30f) ? 127.0f / mx : 0.0f;
    int8_t* q = g_B8 + (size_t)n * K1PAD;
    for (int k = threadIdx.x; k < K1PAD; k += 256) {
        float v = (k < F_IN) ? W[(size_t)k * H1 + n] * s : 0.0f;
        int qi = __float2int_rn(v);
        qi = min(max(qi, -127), 127);
        q[k] = (int8_t)qi;
    }
    if (threadIdx.x == 0) g_sBinv[n] = (mx > 1e-30f) ? mx / 127.0f : 0.0f;
}

// ==================== weight transpose+convert fp16 (layer 2) ====================
__global__ void split_Wt_kernel(const float* __restrict__ W, int K, int N, int Kpad,
                                __half* __restrict__ hi) {
    size_t total = (size_t)N * Kpad;
    size_t i = (size_t)blockIdx.x * blockDim.x + threadIdx.x;
    size_t stride = (size_t)gridDim.x * blockDim.x;
    for (; i < total; i += stride) {
        int n = (int)(i / Kpad), k = (int)(i % Kpad);
        float v = (k < K) ? W[(size_t)k * N + n] : 0.0f;
        hi[i] = __float2half(v);
    }
}

// ==================== GEMM common ====================
#define KC        32
#define SPITCH    80
#define ARR_BYTES (128 * SPITCH)

// ---------- layer-1 int8 GEMM: CTA 128x256, 512 threads, fused scores ----------
#define PITCH8    48
#define A8_BYTES  (128 * PITCH8)     // 6144
#define B8_BYTES  (256 * PITCH8)     // 12288
#define STG8      (A8_BYTES + B8_BYTES)   // 18432
#define G1_SMEM   (2 * STG8)         // 36864

__global__ void __launch_bounds__(512)
gemm1_s8_kernel(__half* __restrict__ C16,
                const float* __restrict__ a_s, const float* __restrict__ a_d) {
    extern __shared__ char smem[];
    const uint32_t sb = smem_u32(smem);
    const int tid = threadIdx.x;
    const int wid = tid >> 5, lane = tid & 31;
    const int warp_m = wid & 3, warp_n = wid >> 2;   // 4 x 4 warps
    const int m0 = blockIdx.y * 128;
    const int n0 = blockIdx.x * 256;
    const int nchunks = K1PAD / KC;   // 46

    // cp.async mapping: A 128 rows x 2 segs (threads 0-255); B 256 rows x 2 segs (all threads)
    const int arow_t = tid >> 1, aseg = tid & 1;
    const uint32_t adst = (uint32_t)arow_t * PITCH8 + aseg * 16;
    const int8_t* asrc = g_A8 + (size_t)(m0 + arow_t) * K1PAD + aseg * 16;
    const int brow_t = tid >> 1, bseg = tid & 1;
    const uint32_t bdst = A8_BYTES + (uint32_t)brow_t * PITCH8 + bseg * 16;
    const int8_t* bsrc = g_B8 + (size_t)(n0 + brow_t) * K1PAD + bseg * 16;

    int acc[2][8][4];
    #pragma unroll
    for (int mi = 0; mi < 2; mi++)
        #pragma unroll
        for (int ni = 0; ni < 8; ni++)
            #pragma unroll
            for (int q = 0; q < 4; q++) acc[mi][ni][q] = 0;

    {
        const uint32_t d = sb;
        if (tid < 256) cp16(d + adst, asrc);
        cp16(d + bdst, bsrc);
        asm volatile("cp.async.commit_group;");
    }

    const int lr4 = lane >> 2, lc4 = (lane & 3) * 4;
    for (int c = 0; c < nchunks; c++) {
        if (c + 1 < nchunks) {
            const uint32_t d = sb + ((c + 1) & 1) * STG8;
            const size_t ko = (size_t)(c + 1) * KC;
            if (tid < 256) cp16(d + adst, asrc + ko);
            cp16(d + bdst, bsrc + ko);
            asm volatile("cp.async.commit_group;");
            asm volatile("cp.async.wait_group 1;");
        } else {
            asm volatile("cp.async.wait_group 0;");
        }
        __syncthreads();

        const uint32_t base = sb + (c & 1) * STG8;
        int a8[2][4], b8[8][2];
        #pragma unroll
        for (int mt = 0; mt < 2; mt++) {
            uint32_t ab = base + (uint32_t)(warp_m * 32 + mt * 16 + lr4) * PITCH8 + lc4;
            a8[mt][0] = lds32(ab);
            a8[mt][1] = lds32(ab + 8 * PITCH8);
            a8[mt][2] = lds32(ab + 16);
            a8[mt][3] = lds32(ab + 8 * PITCH8 + 16);
        }
        #pragma unroll
        for (int ni = 0; ni < 8; ni++) {
            uint32_t bb = base + A8_BYTES + (uint32_t)(warp_n * 64 + ni * 8 + lr4) * PITCH8 + lc4;
            b8[ni][0] = lds32(bb);
            b8[ni][1] = lds32(bb + 16);
        }
        #pragma unroll
        for (int mi = 0; mi < 2; mi++)
            #pragma unroll
            for (int ni = 0; ni < 8; ni++)
                mma_s8(acc[mi][ni], a8[mi], b8[ni]);
        __syncthreads();
    }

    // epilogue: scale, store fp16 h, fused scores
    const int er = lane >> 2, ec = (lane & 3) * 2;
    #pragma unroll
    for (int mi = 0; mi < 2; mi++) {
        const int r0 = m0 + warp_m * 32 + mi * 16 + er;
        const int r1 = r0 + 8;
        const float sa0 = g_sAinv[r0];
        const float sa1 = g_sAinv[r1];
        float ss0 = 0.f, ss1 = 0.f, sd0 = 0.f, sd1 = 0.f;
        #pragma unroll
        for (int ni = 0; ni < 8; ni++) {
            const int cc = n0 + warp_n * 64 + ni * 8 + ec;
            const float sb0 = g_sBinv[cc], sb1 = g_sBinv[cc + 1];
            float f0 = (float)acc[mi][ni][0] * sa0 * sb0;
            float f1 = (float)acc[mi][ni][1] * sa0 * sb1;
            float f2 = (float)acc[mi][ni][2] * sa1 * sb0;
            float f3 = (float)acc[mi][ni][3] * sa1 * sb1;
            __half2 p0, p1;
            p0.x = __float2half(f0); p0.y = __float2half(f1);
            p1.x = __float2half(f2); p1.y = __float2half(f3);
            *(__half2*)(C16 + (size_t)r0 * H1 + cc) = p0;
            *(__half2*)(C16 + (size_t)r1 * H1 + cc) = p1;
            float as0 = a_s[cc], as1 = a_s[cc + 1];
            float ad0 = a_d[cc], ad1 = a_d[cc + 1];
            ss0 += f0 * as0 + f1 * as1;
            ss1 += f2 * as0 + f3 * as1;
            sd0 += f0 * ad0 + f1 * ad1;
            sd1 += f2 * ad0 + f3 * ad1;
        }
        #pragma unroll
        for (int o = 1; o <= 2; o <<= 1) {
            ss0 += __shfl_xor_sync(0xffffffffu, ss0, o);
            ss1 += __shfl_xor_sync(0xffffffffu, ss1, o);
            sd0 += __shfl_xor_sync(0xffffffffu, sd0, o);
            sd1 += __shfl_xor_sync(0xffffffffu, sd1, o);
        }
        if ((lane & 3) == 0) {
            if (r0 < N_NODES) { atomicAdd(&g_ss[r0], ss0); atomicAdd(&g_sd[r0], sd0); }
            if (r1 < N_NODES) { atomicAdd(&g_ss[r1], ss1); atomicAdd(&g_sd[r1], sd1); }
        }
    }
}

// ---------- layer-2 GEMM: fp16 A (cp.async), fp16 B, fp16 out, fused scores ----------
#define STG_BYTES (2 * ARR_BYTES)
#define OFF_A16   0
#define OFF_B16   ARR_BYTES
#define SMEM_DYN  (2 * STG_BYTES)

__global__ void __launch_bounds__(256)
gemm_tc_kernel(const __half* __restrict__ A16,
               const __half* __restrict__ B16,
               __half* __restrict__ C16, int Kpad, int Nc,
               const float* __restrict__ a_s, const float* __restrict__ a_d) {
    extern __shared__ char smem[];
    const uint32_t sb = smem_u32(smem);
    const int tid = threadIdx.x;
    const int wid = tid >> 5, lane = tid & 31;
    const int warp_m = wid & 3, warp_n = wid >> 2;
    const int m0 = blockIdx.y * 128;
    const int n0 = blockIdx.x * 128;
    const int nchunks = Kpad / KC;

    const int row0 = tid >> 2, seg = tid & 3;
    const int row1 = row0 + 64;
    const uint32_t s0 = (uint32_t)row0 * SPITCH + seg * 16;
    const uint32_t s1 = (uint32_t)row1 * SPITCH + seg * 16;
    const size_t gA0 = (size_t)(m0 + row0) * Kpad + seg * 8;
    const size_t gA1 = (size_t)(m0 + row1) * Kpad + seg * 8;
    const size_t gB0 = (size_t)(n0 + row0) * Kpad + seg * 8;
    const size_t gB1 = (size_t)(n0 + row1) * Kpad + seg * 8;

    const int lr = lane & 7, g = lane >> 3;
    const uint32_t offA = (uint32_t)(warp_m * 32 + lr + (g & 1) * 8) * SPITCH + (g >> 1) * 16;
    const uint32_t offB = (uint32_t)(warp_n * 64 + lr + (g >> 1) * 8) * SPITCH + (g & 1) * 16;

    float acc[2][8][4];
    #pragma unroll
    for (int mi = 0; mi < 2; mi++)
        #pragma unroll
        for (int ni = 0; ni < 8; ni++)
            #pragma unroll
            for (int q = 0; q < 4; q++) acc[mi][ni][q] = 0.0f;

    {
        const uint32_t d = sb;
        cp16(d + OFF_A16 + s0, A16 + gA0); cp16(d + OFF_A16 + s1, A16 + gA1);
        cp16(d + OFF_B16 + s0, B16 + gB0); cp16(d + OFF_B16 + s1, B16 + gB1);
        asm volatile("cp.async.commit_group;");
    }

    for (int c = 0; c < nchunks; c++) {
        if (c + 1 < nchunks) {
            const uint32_t d = sb + ((c + 1) & 1) * STG_BYTES;
            const size_t ko = (size_t)(c + 1) * KC;
            cp16(d + OFF_A16 + s0, A16 + gA0 + ko); cp16(d + OFF_A16 + s1, A16 + gA1 + ko);
            cp16(d + OFF_B16 + s0, B16 + gB0 + ko); cp16(d + OFF_B16 + s1, B16 + gB1 + ko);
            asm volatile("cp.async.commit_group;");
            asm volatile("cp.async.wait_group 1;");
        } else {
            asm volatile("cp.async.wait_group 0;");
        }
        __syncthreads();

        const uint32_t base = sb + (c & 1) * STG_BYTES;
        #pragma unroll
        for (int ks = 0; ks < 2; ks++) {
            const uint32_t kadd = ks * 32;
            uint32_t a16[2][4], b16[8][2];
            #pragma unroll
            for (int mt = 0; mt < 2; mt++)
                ldm_x4(a16[mt][0], a16[mt][1], a16[mt][2], a16[mt][3],
                       base + OFF_A16 + offA + mt * 16 * SPITCH + kadd);
            #pragma unroll
            for (int np = 0; np < 4; np++)
                ldm_x4(b16[2*np][0], b16[2*np][1], b16[2*np+1][0], b16[2*np+1][1],
                       base + OFF_B16 + offB + np * 16 * SPITCH + kadd);
            #pragma unroll
            for (int mi = 0; mi < 2; mi++)
                #pragma unroll
                for (int ni = 0; ni < 8; ni++)
                    mma_f16(acc[mi][ni], a16[mi], b16[ni]);
        }
        __syncthreads();
    }

    const int er = lane >> 2, ec = (lane & 3) * 2;
    #pragma unroll
    for (int mi = 0; mi < 2; mi++) {
        const int r_lo = m0 + warp_m * 32 + mi * 16 + er;
        #pragma unroll
        for (int ni = 0; ni < 8; ni++) {
            const int cc = n0 + warp_n * 64 + ni * 8 + ec;
            __half2 p0, p1;
            p0.x = __float2half(acc[mi][ni][0]); p0.y = __float2half(acc[mi][ni][1]);
            p1.x = __float2half(acc[mi][ni][2]); p1.y = __float2half(acc[mi][ni][3]);
            *(__half2*)(C16 + (size_t)r_lo * Nc + cc)       = p0;
            *(__half2*)(C16 + (size_t)(r_lo + 8) * Nc + cc) = p1;
        }
    }
    epilogue_scores(acc, a_s, a_d, m0, n0, warp_m, warp_n, lane);
}

// ==================== alpha prepass (warp per node) ====================
__global__ void __launch_bounds__(256)
alpha_kernel() {
    int node = blockIdx.x * 8 + (threadIdx.x >> 5);
    int lane = threadIdx.x & 31;
    if (node >= N_NODES) return;
    const int beg = g_rowoff[node], end = g_rowoff[node + 1];
    const float sd = g_sd[node];

    float m = -INFINITY;
    for (int i = beg + lane; i < end; i += 32) {
        float e = g_ss[g_csr_src[i]] + sd;
        e = e > 0.0f ? e : 0.2f * e;
        m = fmaxf(m, e);
    }
    #pragma unroll
    for (int o = 16; o > 0; o >>= 1) m = fmaxf(m, __shfl_xor_sync(0xffffffffu, m, o));

    float den = 0.0f;
    for (int i = beg + lane; i < end; i += 32) {
        float e = g_ss[g_csr_src[i]] + sd;
        e = e > 0.0f ? e : 0.2f * e;
        float ee = __expf(e - m);
        g_alpha[i] = ee;
        den += ee;
    }
    #pragma unroll
    for (int o = 16; o > 0; o >>= 1) den += __shfl_xor_sync(0xffffffffu, den, o);
    float inv = 1.0f / den;
    for (int i = beg + lane; i < end; i += 32) g_alpha[i] *= inv;
}

// ==================== weighted gather aggregation ====================
template <int F, int NW, int OUT_F16, int ZERO_S>
__global__ void __launch_bounds__(256)
gat_agg_kernel(const __half* __restrict__ h, const float* __restrict__ bias,
               float* __restrict__ outf, __half* __restrict__ oh) {
    int gw = blockIdx.x * 8 + (threadIdx.x >> 5);
    int lane = threadIdx.x & 31;
    int node = gw / NW, part = gw % NW;
    if (node >= N_NODES) return;
    if (ZERO_S && part == 0 && lane == 0) {
        g_ss[node] = 0.0f;
        g_sd[node] = 0.0f;
    }
    const int beg = g_rowoff[node], end = g_rowoff[node + 1];
    const uint32_t c8 = part * (F / NW) + lane * 8;

    float acc[8];
    #pragma unroll
    for (int q = 0; q < 8; q++) acc[q] = 0.0f;

    int i = beg;
    for (; i + 1 < end; i += 2) {
        int s0 = g_csr_src[i], s1 = g_csr_src[i + 1];
        float w0 = g_alpha[i], w1 = g_alpha[i + 1];
        uint4 r0 = *(const uint4*)(h + (size_t)s0 * F + c8);
        uint4 r1 = *(const uint4*)(h + (size_t)s1 * F + c8);
        const __half2* p0 = (const __half2*)&r0;
        const __half2* p1 = (const __half2*)&r1;
        #pragma unroll
        for (int q = 0; q < 4; q++) {
            float2 v0 = __half22float2(p0[q]);
            float2 v1 = __half22float2(p1[q]);
            acc[2*q+0] += w0 * v0.x + w1 * v1.x;
            acc[2*q+1] += w0 * v0.y + w1 * v1.y;
        }
    }
    if (i < end) {
        int s0 = g_csr_src[i];
        float w0 = g_alpha[i];
        uint4 r0 = *(const uint4*)(h + (size_t)s0 * F + c8);
        const __half2* p0 = (const __half2*)&r0;
        #pragma unroll
        for (int q = 0; q < 4; q++) {
            float2 v0 = __half22float2(p0[q]);
            acc[2*q+0] += w0 * v0.x;
            acc[2*q+1] += w0 * v0.y;
        }
    }

    float v[8];
    #pragma unroll
    for (int q = 0; q < 8; q++) v[q] = fmaxf(acc[q] + bias[c8 + q], 0.0f);
    size_t o = (size_t)node * F + c8;
    if (OUT_F16) {
        uint4 packed;
        __half2* hp = (__half2*)&packed;
        #pragma unroll
        for (int q = 0; q < 4; q++) {
            __half2 p;
            p.x = __float2half(v[2*q]); p.y = __float2half(v[2*q+1]);
            hp[q] = p;
        }
        *(uint4*)(oh + o) = packed;
    } else {
        *(float4*)(outf + o)     = make_float4(v[0], v[1], v[2], v[3]);
        *(float4*)(outf + o + 4) = make_float4(v[4], v[5], v[6], v[7]);
    }
}

// ==================== layer 3: skinny GEMM (smem W) + fused scores ====================
__global__ void __launch_bounds__(256)
gemm3_kernel(const float* __restrict__ A, const float* __restrict__ W,
             float* __restrict__ C,
             const float* __restrict__ a_s, const float* __restrict__ a_d) {
    __shared__ float sW[H2 * NC];
    __shared__ float sAs[NC], sAd[NC];
    for (int i = threadIdx.x; i < H2 * NC; i += blockDim.x) sW[i] = W[i];
    if (threadIdx.x < NC) {
        sAs[threadIdx.x] = a_s[threadIdx.x];
        sAd[threadIdx.x] = a_d[threadIdx.x];
    }
    __syncthreads();
    int node = blockIdx.x * blockDim.x + threadIdx.x;
    if (node >= N_NODES) return;
    const float4* a4 = (const float4*)(A + (size_t)node * H2);
    float acc[NC] = {0,0,0,0,0,0,0};
    #pragma unroll 4
    for (int k4 = 0; k4 < H2 / 4; k4++) {
        float4 a = a4[k4];
        const float* w0 = sW + (k4 * 4) * NC;
        #pragma unroll
        for (int c = 0; c < NC; c++)
            acc[c] += a.x * w0[c] + a.y * w0[NC + c] + a.z * w0[2 * NC + c] + a.w * w0[3 * NC + c];
    }
    float vs = 0.0f, vd = 0.0f;
    #pragma unroll
    for (int c = 0; c < NC; c++) {
        C[(size_t)node * NC + c] = acc[c];
        vs += acc[c] * sAs[c];
        vd += acc[c] * sAd[c];
    }
    g_ss[node] = vs;
    g_sd[node] = vd;
}

__global__ void __launch_bounds__(256)
gat_agg3_final_kernel(const float* __restrict__ h, const float* __restrict__ bias,
                      float* __restrict__ out) {
    int node = blockIdx.x * 8 + (threadIdx.x >> 5);
    int lane = threadIdx.x & 31;
    if (node >= N_NODES) return;
    const int beg = g_rowoff[node], end = g_rowoff[node + 1];
    const float sd = g_sd[node];

    float m = -INFINITY;
    for (int i = beg + lane; i < end; i += 32) {
        float e = g_ss[g_csr_src[i]] + sd;
        e = e > 0.0f ? e : 0.2f * e;
        m = fmaxf(m, e);
    }
    #pragma unroll
    for (int o = 16; o > 0; o >>= 1) m = fmaxf(m, __shfl_xor_sync(0xffffffffu, m, o));

    float acc[NC] = {0,0,0,0,0,0,0};
    float den = 0.0f;
    for (int i = beg + lane; i < end; i += 32) {
        int s = g_csr_src[i];
        float e = g_ss[s] + sd;
        e = e > 0.0f ? e : 0.2f * e;
        float ee = __expf(e - m);
        den += ee;
        const float* hr = h + (size_t)s * NC;
        #pragma unroll
        for (int c = 0; c < NC; c++) acc[c] += ee * hr[c];
    }
    #pragma unroll
    for (int o = 16; o > 0; o >>= 1) {
        den += __shfl_xor_sync(0xffffffffu, den, o);
        #pragma unroll
        for (int c = 0; c < NC; c++) acc[c] += __shfl_xor_sync(0xffffffffu, acc[c], o);
    }
    if (lane == 0) {
        float inv = 1.0f / den;
        float z[NC], mx = -INFINITY;
        #pragma unroll
        for (int c = 0; c < NC; c++) {
            z[c] = acc[c] * inv + bias[c];
            mx = fmaxf(mx, z[c]);
        }
        float ssum = 0.0f;
        #pragma unroll
        for (int c = 0; c < NC; c++) ssum += __expf(z[c] - mx);
        float l = logf(ssum);
        float* o = out + (size_t)node * NC;
        #pragma unroll
        for (int c = 0; c < NC; c++) o[c] = z[c] - mx - l;
    }
}

// ==================== launcher ====================
extern "C" void kernel_launch(void* const* d_in, const int* in_sizes, int n_in,
                              void* d_out, int out_size) {
    const float* x   = (const float*)d_in[0];
    const void*  ei  = d_in[1];
    const float* W1  = (const float*)d_in[2];
    const float* as1 = (const float*)d_in[3];
    const float* ad1 = (const float*)d_in[4];
    const float* b1  = (const float*)d_in[5];
    const float* W2  = (const float*)d_in[6];
    const float* as2 = (const float*)d_in[7];
    const float* ad2 = (const float*)d_in[8];
    const float* b2  = (const float*)d_in[9];
    const float* W3  = (const float*)d_in[10];
    const float* as3 = (const float*)d_in[11];
    const float* ad3 = (const float*)d_in[12];
    const float* b3  = (const float*)d_in[13];
    float* out = (float*)d_out;

    float *buf1, *buf2;
    __half *h16, *a16, *b16b;
    cudaGetSymbolAddress((void**)&buf1, g_buf1);
    cudaGetSymbolAddress((void**)&buf2, g_buf2);
    cudaGetSymbolAddress((void**)&h16, g_h16);
    cudaGetSymbolAddress((void**)&a16, g_A16);
    cudaGetSymbolAddress((void**)&b16b, g_B16b);

    cudaFuncSetAttribute(gemm1_s8_kernel, cudaFuncAttributeMaxDynamicSharedMemorySize, G1_SMEM);
    cudaFuncSetAttribute(gemm_tc_kernel, cudaFuncAttributeMaxDynamicSharedMemorySize, SMEM_DYN);

    const int BT = 256;
    const int edge_blocks      = (NE + BT - 1) / BT;
    const int node_warp_blocks = (N_NODES + (BT / 32) - 1) / (BT / 32);
    const int node_blocks      = (N_NODES + BT - 1) / BT;
    const int agg1_blocks      = (N_NODES * 2 + 7) / 8;

    // ---- fork: CSR build + W2 split on side stream ----
    cudaStream_t s2;
    cudaStreamCreateWithFlags(&s2, cudaStreamNonBlocking);
    cudaEvent_t evRoot, evSide;
    cudaEventCreateWithFlags(&evRoot, cudaEventDisableTiming);
    cudaEventCreateWithFlags(&evSide, cudaEventDisableTiming);

    cudaEventRecord(evRoot, 0);
    cudaStreamWaitEvent(s2, evRoot, 0);

    split_Wt_kernel<<<512, BT, 0, s2>>>(W2, H1, H2, H1, b16b);
    init_kernel<<<node_blocks, BT, 0, s2>>>((const unsigned int*)ei);
    prep_edges_kernel<<<edge_blocks, BT, 0, s2>>>(ei);
    reduce_deg_kernel<<<NB, 256, 0, s2>>>();
    scan_bsums_kernel<<<1, 256, 0, s2>>>();
    scan_write_kernel<<<NB, 256, 0, s2>>>();
    scatter_kernel<<<edge_blocks, BT, 0, s2>>>();
    cudaEventRecord(evSide, s2);

    // main stream: layer-1 int8 GEMM chain
    zero_s_kernel<<<node_blocks, BT>>>();
    rowquant_kernel<<<MPAD, BT>>>(x);
    wquant_kernel<<<H1, BT>>>(W1);
    gemm1_s8_kernel<<<dim3(H1 / 256, MPAD / 128), 512, G1_SMEM>>>(h16, as1, ad1);

    cudaStreamWaitEvent(0, evSide, 0);
    alpha_kernel<<<node_warp_blocks, BT>>>();
    gat_agg_kernel<H1, 2, 1, 1><<<agg1_blocks, BT>>>(h16, b1, nullptr, a16);

    // ---------------- layer 2 ----------------
    gemm_tc_kernel<<<dim3(H2 / 128, MPAD / 128), BT, SMEM_DYN>>>(a16, b16b, h16, H1, H2, as2, ad2);
    alpha_kernel<<<node_warp_blocks, BT>>>();
    gat_agg_kernel<H2, 1, 0, 0><<<node_warp_blocks, BT>>>(h16, b2, buf2, nullptr);

    // ---------------- layer 3 ----------------
    gemm3_kernel<<<node_blocks, BT>>>(buf2, W3, buf1, as3, ad3);
    gat_agg3_final_kernel<<<node_warp_blocks, BT>>>(buf1, b3, out);

    cudaEventDestroy(evRoot);
    cudaEventDestroy(evSide);
    cudaStreamDestroy(s2);
}